// round 6
// baseline (speedup 1.0000x reference)
#include <cuda_runtime.h>
#include <math.h>
#include <stdint.h>

// Problem constants
#define HID   2048
#define NH    16
#define NKV   4
#define HD    128
#define SEQ   1024
#define NB    4
#define NT    4096
#define QKV_N 3072
#define FFI   8192
#define EPS   1e-6f
#define NEGF  (-1e30f)

// ---------------- scratch ----------------
__device__ float g_h   [(size_t)NT * HID];
__device__ float g_qkv [(size_t)NT * QKV_N];
__device__ float g_aout[(size_t)NT * HID];
__device__ float g_h1  [(size_t)NT * HID];
__device__ float g_h2  [(size_t)NT * HID];
__device__ float g_gu  [(size_t)NT * 2 * FFI];
__device__ float g_act [(size_t)NT * FFI];
// RNA-rounded (tf32-exact) copies of the weights, same layout as the originals
__device__ float g_wqkvR[(size_t)HID * QKV_N];
__device__ float g_woR  [(size_t)HID * HID];
__device__ float g_wguR [(size_t)HID * 2 * FFI];
__device__ float g_wdnR [(size_t)FFI * HID];

// ---------------- helpers ----------------
__device__ __forceinline__ uint32_t f2tf(float f) {
    uint32_t u;
    asm("cvt.rna.tf32.f32 %0, %1;" : "=r"(u) : "f"(f));
    return u;
}
__device__ __forceinline__ float tfr(float f) { return __uint_as_float(f2tf(f)); }

__device__ __forceinline__ void mma_tf32(float* d, const uint32_t* a, const uint32_t* b) {
    asm volatile(
        "mma.sync.aligned.m16n8k8.row.col.f32.tf32.tf32.f32 "
        "{%0,%1,%2,%3}, {%4,%5,%6,%7}, {%8,%9}, {%0,%1,%2,%3};\n"
        : "+f"(d[0]), "+f"(d[1]), "+f"(d[2]), "+f"(d[3])
        : "r"(a[0]), "r"(a[1]), "r"(a[2]), "r"(a[3]), "r"(b[0]), "r"(b[1]));
}

__device__ __forceinline__ void cp_async16(void* s, const void* g) {
    uint32_t sa = (uint32_t)__cvta_generic_to_shared(s);
    asm volatile("cp.async.cg.shared.global [%0], [%1], 16;\n" :: "r"(sa), "l"(g));
}
#define CP_COMMIT() asm volatile("cp.async.commit_group;\n")

// ---------------- RNA round-copy (weights -> tf32-exact fp32) ----------------
__global__ void __launch_bounds__(256) roundcopy_kernel(const float* __restrict__ s,
                                                        float* __restrict__ d) {
    const size_t i = ((size_t)blockIdx.x * 256 + threadIdx.x) * 4;
    const float4 v = *(const float4*)(s + i);
    float4 r = make_float4(tfr(v.x), tfr(v.y), tfr(v.z), tfr(v.w));
    *(float4*)(d + i) = r;
}

// ---------------- TF32 tensor-core GEMM (legacy mma path) ----------------
// C[M,N] = A[M,K] @ B[K,N] (+R).  Block 128x256, BK=16, 256 threads.
// 8 warps in 2x4 grid, warp tile 64x64 = 4x8 m16n8k8 fragments.
// Operands MUST be tf32-exact fp32 (pre-rounded): fragments loaded as raw bits.
#define ASP 20      // A smem pitch (floats): (20g+c)%32 all-distinct -> conflict-free
#define BSP 264     // B smem pitch: 264%32=8 -> (8c+g)%32 all-distinct -> conflict-free
#define NSTAGE 3
#define GEMM_SMEM (NSTAGE * (128 * ASP + 16 * BSP) * 4)

template <int EPI>
__global__ void __launch_bounds__(256, 1) tf32gemm_kernel(const float* __restrict__ A,
                                                          const float* __restrict__ B,
                                                          const float* __restrict__ R,
                                                          float* __restrict__ C,
                                                          int M, int N, int K) {
    extern __shared__ float sm[];
    float* AsBase = sm;                          // [NSTAGE][128][ASP]
    float* BsBase = sm + NSTAGE * 128 * ASP;     // [NSTAGE][16][BSP]

    const int tid  = threadIdx.x;
    const int bm   = blockIdx.y * 128;
    const int bn   = blockIdx.x * 256;
    const int lane = tid & 31;
    const int warp = tid >> 5;
    const int g = lane >> 2;
    const int c = lane & 3;
    const int wm = (warp >> 2) * 64;
    const int wn = (warp & 3) * 64;

    float acc[4][8][4];
#pragma unroll
    for (int mi = 0; mi < 4; mi++)
#pragma unroll
        for (int ni = 0; ni < 8; ni++)
#pragma unroll
            for (int r = 0; r < 4; r++) acc[mi][ni][r] = 0.0f;

    const int ntiles = K >> 4;

    auto load_tile = [&](int t, int b) {
        float* Ab = AsBase + b * 128 * ASP;
        float* Bb = BsBase + b * 16 * BSP;
        const int kof = t << 4;
#pragma unroll
        for (int i = 0; i < 2; i++) {
            const int p = tid + i * 256;
            const int row = p >> 2, kq = (p & 3) << 2;
            cp_async16(Ab + row * ASP + kq, A + (size_t)(bm + row) * K + kof + kq);
        }
#pragma unroll
        for (int i = 0; i < 4; i++) {
            const int p = tid + i * 256;
            const int kr = p >> 6, c4 = (p & 63) << 2;
            cp_async16(Bb + kr * BSP + c4, B + (size_t)(kof + kr) * N + bn + c4);
        }
        CP_COMMIT();
    };

    load_tile(0, 0);
    load_tile(1, 1);
    load_tile(2, 2);

    for (int t = 0; t < ntiles; t++) {
        const int buf = t % NSTAGE;
        const int rem = ntiles - 1 - t;     // commits issued after tile t's
        if (rem >= 2)      asm volatile("cp.async.wait_group 2;\n");
        else if (rem == 1) asm volatile("cp.async.wait_group 1;\n");
        else               asm volatile("cp.async.wait_group 0;\n");
        __syncthreads();

        const float* Ab = AsBase + buf * 128 * ASP;
        const float* Bb = BsBase + buf * 16 * BSP;
#pragma unroll
        for (int ks = 0; ks < 2; ks++) {
            const int k0 = ks << 3;
            uint32_t af[4][4], bf[8][2];
#pragma unroll
            for (int mi = 0; mi < 4; mi++) {
                const int row = wm + mi * 16 + g;
                af[mi][0] = __float_as_uint(Ab[row * ASP + k0 + c]);
                af[mi][1] = __float_as_uint(Ab[(row + 8) * ASP + k0 + c]);
                af[mi][2] = __float_as_uint(Ab[row * ASP + k0 + c + 4]);
                af[mi][3] = __float_as_uint(Ab[(row + 8) * ASP + k0 + c + 4]);
            }
#pragma unroll
            for (int ni = 0; ni < 8; ni++) {
                const int col = wn + ni * 8 + g;
                bf[ni][0] = __float_as_uint(Bb[(k0 + c) * BSP + col]);
                bf[ni][1] = __float_as_uint(Bb[(k0 + c + 4) * BSP + col]);
            }
#pragma unroll
            for (int mi = 0; mi < 4; mi++)
#pragma unroll
                for (int ni = 0; ni < 8; ni++)
                    mma_tf32(acc[mi][ni], af[mi], bf[ni]);
        }
        __syncthreads();
        if (t + NSTAGE < ntiles) load_tile(t + NSTAGE, buf);
    }

    // epilogue
#pragma unroll
    for (int mi = 0; mi < 4; mi++) {
#pragma unroll
        for (int ni = 0; ni < 8; ni++) {
            const int row = bm + wm + mi * 16 + g;
            const int col = bn + wn + ni * 8 + 2 * c;
            const size_t o0 = (size_t)row * N + col;
            const size_t o1 = (size_t)(row + 8) * N + col;
            float2 v0 = make_float2(acc[mi][ni][0], acc[mi][ni][1]);
            float2 v1 = make_float2(acc[mi][ni][2], acc[mi][ni][3]);
            if (EPI == 1) {
                float2 r0 = *(const float2*)(R + o0);
                float2 r1 = *(const float2*)(R + o1);
                v0.x += r0.x; v0.y += r0.y;
                v1.x += r1.x; v1.y += r1.y;
            }
            *(float2*)(C + o0) = v0;
            *(float2*)(C + o1) = v1;
        }
    }
}

// ---------------- RMSNorm (output RNA-rounded to tf32) ----------------
__global__ void __launch_bounds__(256) rmsnorm_kernel(const float* __restrict__ x,
                                                      const float* __restrict__ w,
                                                      float* __restrict__ out) {
    const int row = blockIdx.x;
    const int tid = threadIdx.x;
    const float4* xr = (const float4*)(x + (size_t)row * HID);
    const float4* wr = (const float4*)w;
    float4* orow = (float4*)(out + (size_t)row * HID);

    float4 v0 = xr[tid];
    float4 v1 = xr[tid + 256];
    float ss = v0.x*v0.x + v0.y*v0.y + v0.z*v0.z + v0.w*v0.w
             + v1.x*v1.x + v1.y*v1.y + v1.z*v1.z + v1.w*v1.w;

    __shared__ float red[256];
    red[tid] = ss;
    __syncthreads();
    for (int s = 128; s > 0; s >>= 1) {
        if (tid < s) red[tid] += red[tid + s];
        __syncthreads();
    }
    const float inv = rsqrtf(red[0] * (1.0f / HID) + EPS);

    float4 w0 = wr[tid], w1 = wr[tid + 256];
    float4 o0 = make_float4(tfr(v0.x*inv*w0.x), tfr(v0.y*inv*w0.y), tfr(v0.z*inv*w0.z), tfr(v0.w*inv*w0.w));
    float4 o1 = make_float4(tfr(v1.x*inv*w1.x), tfr(v1.y*inv*w1.y), tfr(v1.z*inv*w1.z), tfr(v1.w*inv*w1.w));
    orow[tid]       = o0;
    orow[tid + 256] = o1;
}

// ---------------- RoPE ----------------
__global__ void rope_kernel(float* __restrict__ qkv, const int* __restrict__ pos) {
    const int t  = blockIdx.x;
    const int hh = blockIdx.y;
    const int i  = threadIdx.x;
    const float p = (float)pos[t & (SEQ - 1)];
    const float inv_freq = powf(10000.0f, -((float)i) / 64.0f);
    float sn, cs;
    sincosf(p * inv_freq, &sn, &cs);
    float* vp = qkv + (size_t)t * QKV_N + hh * HD;
    const float t1 = vp[i];
    const float t2 = vp[i + 64];
    vp[i]      = t1 * cs - t2 * sn;
    vp[i + 64] = t2 * cs + t1 * sn;
}

// ---------------- Flash attention (fp32, causal, GQA) ----------------
#define ATT_SMEM ((3 * 64 * 128 + 64 * 64 + 3 * 64) * 4)

__global__ void __launch_bounds__(256) attn_kernel(const float* __restrict__ qkv,
                                                   float* __restrict__ aout) {
    const int qt = blockIdx.x, h = blockIdx.y, b = blockIdx.z;
    const int kvh = h >> 2;

    extern __shared__ float smf[];
    float* Qs   = smf;
    float* Kst  = Qs + 64 * 128;
    float* Vs   = Kst + 128 * 64;
    float* Ss   = Vs + 64 * 128;
    float* rowm = Ss + 64 * 64;
    float* rowl = rowm + 64;
    float* rowa = rowl + 64;

    const int tid = threadIdx.x;
    const int q0 = qt * 64;

    for (int i = tid; i < 64 * 32; i += 256) {
        int r = i >> 5, c4 = i & 31;
        *(float4*)&Qs[r * 128 + c4 * 4] =
            *(const float4*)(qkv + (size_t)(b * SEQ + q0 + r) * QKV_N + h * HD + c4 * 4);
    }
    if (tid < 64) { rowm[tid] = NEGF; rowl[tid] = 0.0f; }

    const int ty = tid >> 4, tx = tid & 15;
    const int r0 = ty * 4;
    float o[4][8];
#pragma unroll
    for (int a = 0; a < 4; a++)
#pragma unroll
        for (int j = 0; j < 8; j++) o[a][j] = 0.0f;
    __syncthreads();

    const float scale = 0.0883883476483184f;

    for (int kt = 0; kt <= qt; kt++) {
        const int k0 = kt * 64;
        for (int i = tid; i < 2048; i += 256) {
            int r = i & 63, c4 = i >> 6;
            float4 kk = *(const float4*)(qkv + (size_t)(b * SEQ + k0 + r) * QKV_N
                                         + NH * HD + kvh * HD + c4 * 4);
            int d0 = c4 * 4;
            Kst[(d0 + 0) * 64 + r] = kk.x;
            Kst[(d0 + 1) * 64 + r] = kk.y;
            Kst[(d0 + 2) * 64 + r] = kk.z;
            Kst[(d0 + 3) * 64 + r] = kk.w;
        }
        for (int i = tid; i < 2048; i += 256) {
            int r = i >> 5, c4 = i & 31;
            *(float4*)&Vs[r * 128 + c4 * 4] =
                *(const float4*)(qkv + (size_t)(b * SEQ + k0 + r) * QKV_N
                                 + (NH + NKV) * HD + kvh * HD + c4 * 4);
        }
        __syncthreads();

        float s[4][4];
#pragma unroll
        for (int a = 0; a < 4; a++)
#pragma unroll
            for (int j = 0; j < 4; j++) s[a][j] = 0.0f;

#pragma unroll 4
        for (int k = 0; k < 128; k++) {
            float qa[4], kb[4];
#pragma unroll
            for (int a = 0; a < 4; a++) qa[a] = Qs[(r0 + a) * 128 + k];
#pragma unroll
            for (int j = 0; j < 4; j++) kb[j] = Kst[k * 64 + tx * 4 + j];
#pragma unroll
            for (int a = 0; a < 4; a++)
#pragma unroll
                for (int j = 0; j < 4; j++) s[a][j] += qa[a] * kb[j];
        }
        const bool diag = (kt == qt);
#pragma unroll
        for (int a = 0; a < 4; a++)
#pragma unroll
            for (int j = 0; j < 4; j++) {
                float v = s[a][j] * scale;
                if (diag && (r0 + a) < (tx * 4 + j)) v = NEGF;
                Ss[(r0 + a) * 64 + tx * 4 + j] = v;
            }
        __syncthreads();

        {
            const int row = tid >> 2, l4 = tid & 3;
            float mx = NEGF;
            for (int cc = l4; cc < 64; cc += 4) mx = fmaxf(mx, Ss[row * 64 + cc]);
            mx = fmaxf(mx, __shfl_xor_sync(0xffffffffu, mx, 1));
            mx = fmaxf(mx, __shfl_xor_sync(0xffffffffu, mx, 2));
            const float mold = rowm[row];
            const float mnew = fmaxf(mold, mx);
            float ls = 0.0f;
            for (int cc = l4; cc < 64; cc += 4) {
                float p = expf(Ss[row * 64 + cc] - mnew);
                Ss[row * 64 + cc] = p;
                ls += p;
            }
            ls += __shfl_xor_sync(0xffffffffu, ls, 1);
            ls += __shfl_xor_sync(0xffffffffu, ls, 2);
            if (l4 == 0) {
                const float alpha = expf(mold - mnew);
                rowa[row] = alpha;
                rowl[row] = rowl[row] * alpha + ls;
                rowm[row] = mnew;
            }
        }
        __syncthreads();

        float al[4];
#pragma unroll
        for (int a = 0; a < 4; a++) al[a] = rowa[r0 + a];
#pragma unroll
        for (int a = 0; a < 4; a++)
#pragma unroll
            for (int j = 0; j < 8; j++) o[a][j] *= al[a];

#pragma unroll 2
        for (int kk = 0; kk < 64; kk++) {
            float p[4];
#pragma unroll
            for (int a = 0; a < 4; a++) p[a] = Ss[(r0 + a) * 64 + kk];
            float4 v0 = *(const float4*)&Vs[kk * 128 + tx * 8];
            float4 v1 = *(const float4*)&Vs[kk * 128 + tx * 8 + 4];
            float vv[8] = {v0.x, v0.y, v0.z, v0.w, v1.x, v1.y, v1.z, v1.w};
#pragma unroll
            for (int a = 0; a < 4; a++)
#pragma unroll
                for (int j = 0; j < 8; j++) o[a][j] += p[a] * vv[j];
        }
        __syncthreads();
    }

    float il[4];
#pragma unroll
    for (int a = 0; a < 4; a++) il[a] = 1.0f / rowl[r0 + a];
#pragma unroll
    for (int a = 0; a < 4; a++) {
        size_t off = (size_t)(b * SEQ + q0 + r0 + a) * HID + h * HD + tx * 8;
        float4 o0 = make_float4(tfr(o[a][0] * il[a]), tfr(o[a][1] * il[a]),
                                tfr(o[a][2] * il[a]), tfr(o[a][3] * il[a]));
        float4 o1 = make_float4(tfr(o[a][4] * il[a]), tfr(o[a][5] * il[a]),
                                tfr(o[a][6] * il[a]), tfr(o[a][7] * il[a]));
        *(float4*)(aout + off)     = o0;
        *(float4*)(aout + off + 4) = o1;
    }
}

// ---------------- SiLU(gate)*up (output RNA-rounded) ----------------
__global__ void __launch_bounds__(256) silu_kernel(const float* __restrict__ gu,
                                                   float* __restrict__ act) {
    size_t idx = (size_t)blockIdx.x * 256 + threadIdx.x;
    int row = (int)(idx / (FFI / 4));
    int c   = (int)(idx % (FFI / 4));
    const float4 g = *(const float4*)(gu + (size_t)row * 2 * FFI + c * 4);
    const float4 u = *(const float4*)(gu + (size_t)row * 2 * FFI + FFI + c * 4);
    float4 r;
    r.x = tfr(g.x / (1.0f + expf(-g.x)) * u.x);
    r.y = tfr(g.y / (1.0f + expf(-g.y)) * u.y);
    r.z = tfr(g.z / (1.0f + expf(-g.z)) * u.z);
    r.w = tfr(g.w / (1.0f + expf(-g.w)) * u.w);
    *(float4*)(act + (size_t)row * FFI + c * 4) = r;
}

// ---------------- launch ----------------
extern "C" void kernel_launch(void* const* d_in, const int* in_sizes, int n_in,
                              void* d_out, int out_size) {
    const float* x    = (const float*)d_in[0];
    const float* ln1w = (const float*)d_in[1];
    const float* wqkv = (const float*)d_in[2];
    const float* wo   = (const float*)d_in[3];
    const float* ln2w = (const float*)d_in[4];
    const float* wgu  = (const float*)d_in[5];
    const float* wdn  = (const float*)d_in[6];
    const int*   pos  = (const int*)d_in[7];
    float* out = (float*)d_out;

    void *ph, *pqkv, *paout, *ph1, *ph2, *pgu, *pact, *pwq, *pwo, *pwg, *pwd;
    cudaGetSymbolAddress(&ph,    g_h);
    cudaGetSymbolAddress(&pqkv,  g_qkv);
    cudaGetSymbolAddress(&paout, g_aout);
    cudaGetSymbolAddress(&ph1,   g_h1);
    cudaGetSymbolAddress(&ph2,   g_h2);
    cudaGetSymbolAddress(&pgu,   g_gu);
    cudaGetSymbolAddress(&pact,  g_act);
    cudaGetSymbolAddress(&pwq,   g_wqkvR);
    cudaGetSymbolAddress(&pwo,   g_woR);
    cudaGetSymbolAddress(&pwg,   g_wguR);
    cudaGetSymbolAddress(&pwd,   g_wdnR);
    float* h     = (float*)ph;
    float* qkv   = (float*)pqkv;
    float* aout  = (float*)paout;
    float* h1    = (float*)ph1;
    float* h2    = (float*)ph2;
    float* gu    = (float*)pgu;
    float* act   = (float*)pact;
    float* wqkvR = (float*)pwq;
    float* woR   = (float*)pwo;
    float* wguR  = (float*)pwg;
    float* wdnR  = (float*)pwd;

    cudaFuncSetAttribute(attn_kernel, cudaFuncAttributeMaxDynamicSharedMemorySize, ATT_SMEM);
    cudaFuncSetAttribute(tf32gemm_kernel<0>, cudaFuncAttributeMaxDynamicSharedMemorySize, GEMM_SMEM);
    cudaFuncSetAttribute(tf32gemm_kernel<1>, cudaFuncAttributeMaxDynamicSharedMemorySize, GEMM_SMEM);

    // 0. RNA-round weights once (tf32-exact bits; GEMM then loads raw)
    roundcopy_kernel<<<(HID * QKV_N / 4) / 256, 256>>>(wqkv, wqkvR);
    roundcopy_kernel<<<(HID * HID / 4) / 256, 256>>>(wo, woR);
    roundcopy_kernel<<<(HID * 2 * FFI / 4) / 256, 256>>>(wgu, wguR);
    roundcopy_kernel<<<(FFI * HID / 4) / 256, 256>>>(wdn, wdnR);

    // 1. h = rmsnorm(x)
    rmsnorm_kernel<<<NT, 256>>>(x, ln1w, h);
    // 2. qkv = h @ wqkv
    tf32gemm_kernel<0><<<dim3(QKV_N / 256, NT / 128), 256, GEMM_SMEM>>>(h, wqkvR, nullptr, qkv, NT, QKV_N, HID);
    // 3. rope
    rope_kernel<<<dim3(NT, NH + NKV), 64>>>(qkv, pos);
    // 4. attention
    attn_kernel<<<dim3(SEQ / 64, NH, NB), 256, ATT_SMEM>>>(qkv, aout);
    // 5. h1 = x + aout @ wo
    tf32gemm_kernel<1><<<dim3(HID / 256, NT / 128), 256, GEMM_SMEM>>>(aout, woR, x, h1, NT, HID, HID);
    // 6. h2 = rmsnorm(h1)
    rmsnorm_kernel<<<NT, 256>>>(h1, ln2w, h2);
    // 7. gu = h2 @ w_gate_up
    tf32gemm_kernel<0><<<dim3(2 * FFI / 256, NT / 128), 256, GEMM_SMEM>>>(h2, wguR, nullptr, gu, NT, 2 * FFI, HID);
    // 8. act = silu(gate)*up
    silu_kernel<<<(NT * FFI / 4) / 256, 256>>>(gu, act);
    // 9. out = h1 + act @ w_down
    tf32gemm_kernel<1><<<dim3(HID / 256, NT / 128), 256, GEMM_SMEM>>>(act, wdnR, h1, out, NT, HID, FFI);
}

// round 7
// speedup vs baseline: 1.6236x; 1.6236x over previous
#include <cuda_runtime.h>
#include <math.h>
#include <stdint.h>

// Problem constants
#define HID   2048
#define NH    16
#define NKV   4
#define HD    128
#define SEQ   1024
#define NB    4
#define NT    4096
#define QKV_N 3072
#define FFI   8192
#define EPS   1e-6f
#define NEGF  (-1e30f)

// ---------------- scratch ----------------
__device__ float g_h   [(size_t)NT * HID];
__device__ float g_qkv [(size_t)NT * QKV_N];
__device__ float g_aout[(size_t)NT * HID];
__device__ float g_h1  [(size_t)NT * HID];
__device__ float g_h2  [(size_t)NT * HID];
__device__ float g_gu  [(size_t)NT * 2 * FFI];
__device__ float g_act [(size_t)NT * FFI];
// RNA-rounded (tf32-exact) copies of the weights, same layout as the originals
__device__ float g_wqkvR[(size_t)HID * QKV_N];
__device__ float g_woR  [(size_t)HID * HID];
__device__ float g_wguR [(size_t)HID * 2 * FFI];
__device__ float g_wdnR [(size_t)FFI * HID];

// ---------------- helpers ----------------
__device__ __forceinline__ uint32_t f2tf(float f) {
    uint32_t u;
    asm("cvt.rna.tf32.f32 %0, %1;" : "=r"(u) : "f"(f));
    return u;
}
__device__ __forceinline__ float tfr(float f) { return __uint_as_float(f2tf(f)); }

__device__ __forceinline__ void mma_tf32(float* d, const uint32_t* a, const uint32_t* b) {
    asm volatile(
        "mma.sync.aligned.m16n8k8.row.col.f32.tf32.tf32.f32 "
        "{%0,%1,%2,%3}, {%4,%5,%6,%7}, {%8,%9}, {%0,%1,%2,%3};\n"
        : "+f"(d[0]), "+f"(d[1]), "+f"(d[2]), "+f"(d[3])
        : "r"(a[0]), "r"(a[1]), "r"(a[2]), "r"(a[3]), "r"(b[0]), "r"(b[1]));
}

__device__ __forceinline__ void cp_async16(void* s, const void* g) {
    uint32_t sa = (uint32_t)__cvta_generic_to_shared(s);
    asm volatile("cp.async.cg.shared.global [%0], [%1], 16;\n" :: "r"(sa), "l"(g));
}

// ---------------- RNA round-copy (weights -> tf32-exact fp32) ----------------
__global__ void __launch_bounds__(256) roundcopy_kernel(const float* __restrict__ s,
                                                        float* __restrict__ d) {
    const size_t i = ((size_t)blockIdx.x * 256 + threadIdx.x) * 4;
    const float4 v = *(const float4*)(s + i);
    float4 r = make_float4(tfr(v.x), tfr(v.y), tfr(v.z), tfr(v.w));
    *(float4*)(d + i) = r;
}

// ---------------- TF32 tensor-core GEMM (round-4 geometry, raw-bit loads) ----
// C[M,N] = A[M,K] @ B[K,N] (+R).  128x128 block, BK=16, 256 threads.
// 8 warps in 2x4 grid, warp tile 64x32 = 4x4 m16n8k8 fragments.
// Operands MUST be tf32-exact fp32 (pre-rounded); fragments are raw bits.
template <int EPI>
__global__ void __launch_bounds__(256, 2) tf32gemm_kernel(const float* __restrict__ A,
                                                          const float* __restrict__ B,
                                                          const float* __restrict__ R,
                                                          float* __restrict__ C,
                                                          int M, int N, int K) {
    __shared__ float As[2][128][20];   // pitch 20 -> conflict-free frag loads
    __shared__ float Bs[2][16][136];   // pitch 136 -> conflict-free frag loads

    const int tid  = threadIdx.x;
    const int bm   = blockIdx.y * 128;
    const int bn   = blockIdx.x * 128;
    const int lane = tid & 31;
    const int warp = tid >> 5;
    const int g = lane >> 2;
    const int c = lane & 3;
    const int wm = (warp >> 2) * 64;
    const int wn = (warp & 3) * 32;

    const int ar0 = tid >> 2,        ac0 = (tid & 3) << 2;
    const int ar1 = (tid + 256) >> 2;
    const int br0 = tid >> 5,        bc0 = (tid & 31) << 2;
    const int br1 = (tid + 256) >> 5;

    float acc[4][4][4];
#pragma unroll
    for (int mi = 0; mi < 4; mi++)
#pragma unroll
        for (int ni = 0; ni < 4; ni++)
#pragma unroll
            for (int r = 0; r < 4; r++) acc[mi][ni][r] = 0.0f;

    const int ntiles = K >> 4;

    {
        cp_async16(&As[0][ar0][ac0], A + (size_t)(bm + ar0) * K + ac0);
        cp_async16(&As[0][ar1][ac0], A + (size_t)(bm + ar1) * K + ac0);
        cp_async16(&Bs[0][br0][bc0], B + (size_t)br0 * N + bn + bc0);
        cp_async16(&Bs[0][br1][bc0], B + (size_t)br1 * N + bn + bc0);
        asm volatile("cp.async.commit_group;\n");
    }

    for (int t = 0; t < ntiles; t++) {
        const int buf = t & 1;
        if (t + 1 < ntiles) {
            const int nb = (t + 1) & 1;
            const int kof = (t + 1) << 4;
            cp_async16(&As[nb][ar0][ac0], A + (size_t)(bm + ar0) * K + kof + ac0);
            cp_async16(&As[nb][ar1][ac0], A + (size_t)(bm + ar1) * K + kof + ac0);
            cp_async16(&Bs[nb][br0][bc0], B + (size_t)(kof + br0) * N + bn + bc0);
            cp_async16(&Bs[nb][br1][bc0], B + (size_t)(kof + br1) * N + bn + bc0);
            asm volatile("cp.async.commit_group;\n");
            asm volatile("cp.async.wait_group 1;\n");
        } else {
            asm volatile("cp.async.wait_group 0;\n");
        }
        __syncthreads();

#pragma unroll
        for (int ks = 0; ks < 2; ks++) {
            const int k0 = ks << 3;
            uint32_t af[4][4], bf[4][2];
#pragma unroll
            for (int mi = 0; mi < 4; mi++) {
                const int row = wm + mi * 16 + g;
                af[mi][0] = __float_as_uint(As[buf][row    ][k0 + c    ]);
                af[mi][1] = __float_as_uint(As[buf][row + 8][k0 + c    ]);
                af[mi][2] = __float_as_uint(As[buf][row    ][k0 + c + 4]);
                af[mi][3] = __float_as_uint(As[buf][row + 8][k0 + c + 4]);
            }
#pragma unroll
            for (int ni = 0; ni < 4; ni++) {
                const int col = wn + ni * 8 + g;
                bf[ni][0] = __float_as_uint(Bs[buf][k0 + c    ][col]);
                bf[ni][1] = __float_as_uint(Bs[buf][k0 + c + 4][col]);
            }
#pragma unroll
            for (int mi = 0; mi < 4; mi++)
#pragma unroll
                for (int ni = 0; ni < 4; ni++)
                    mma_tf32(acc[mi][ni], af[mi], bf[ni]);
        }
        __syncthreads();
    }

    // epilogue
#pragma unroll
    for (int mi = 0; mi < 4; mi++) {
#pragma unroll
        for (int ni = 0; ni < 4; ni++) {
            const int row = bm + wm + mi * 16 + g;
            const int col = bn + wn + ni * 8 + 2 * c;
            const size_t o0 = (size_t)row * N + col;
            const size_t o1 = (size_t)(row + 8) * N + col;
            float2 v0 = make_float2(acc[mi][ni][0], acc[mi][ni][1]);
            float2 v1 = make_float2(acc[mi][ni][2], acc[mi][ni][3]);
            if (EPI == 1) {
                float2 r0 = *(const float2*)(R + o0);
                float2 r1 = *(const float2*)(R + o1);
                v0.x += r0.x; v0.y += r0.y;
                v1.x += r1.x; v1.y += r1.y;
            }
            *(float2*)(C + o0) = v0;
            *(float2*)(C + o1) = v1;
        }
    }
}

// ---------------- RMSNorm (output RNA-rounded to tf32) ----------------
__global__ void __launch_bounds__(256) rmsnorm_kernel(const float* __restrict__ x,
                                                      const float* __restrict__ w,
                                                      float* __restrict__ out) {
    const int row = blockIdx.x;
    const int tid = threadIdx.x;
    const float4* xr = (const float4*)(x + (size_t)row * HID);
    const float4* wr = (const float4*)w;
    float4* orow = (float4*)(out + (size_t)row * HID);

    float4 v0 = xr[tid];
    float4 v1 = xr[tid + 256];
    float ss = v0.x*v0.x + v0.y*v0.y + v0.z*v0.z + v0.w*v0.w
             + v1.x*v1.x + v1.y*v1.y + v1.z*v1.z + v1.w*v1.w;

    __shared__ float red[256];
    red[tid] = ss;
    __syncthreads();
    for (int s = 128; s > 0; s >>= 1) {
        if (tid < s) red[tid] += red[tid + s];
        __syncthreads();
    }
    const float inv = rsqrtf(red[0] * (1.0f / HID) + EPS);

    float4 w0 = wr[tid], w1 = wr[tid + 256];
    float4 o0 = make_float4(tfr(v0.x*inv*w0.x), tfr(v0.y*inv*w0.y), tfr(v0.z*inv*w0.z), tfr(v0.w*inv*w0.w));
    float4 o1 = make_float4(tfr(v1.x*inv*w1.x), tfr(v1.y*inv*w1.y), tfr(v1.z*inv*w1.z), tfr(v1.w*inv*w1.w));
    orow[tid]       = o0;
    orow[tid + 256] = o1;
}

// ---------------- RoPE ----------------
__global__ void rope_kernel(float* __restrict__ qkv, const int* __restrict__ pos) {
    const int t  = blockIdx.x;
    const int hh = blockIdx.y;
    const int i  = threadIdx.x;
    const float p = (float)pos[t & (SEQ - 1)];
    const float inv_freq = powf(10000.0f, -((float)i) / 64.0f);
    float sn, cs;
    sincosf(p * inv_freq, &sn, &cs);
    float* vp = qkv + (size_t)t * QKV_N + hh * HD;
    const float t1 = vp[i];
    const float t2 = vp[i + 64];
    vp[i]      = t1 * cs - t2 * sn;
    vp[i + 64] = t2 * cs + t1 * sn;
}

// ---------------- Flash attention (fp32, causal, GQA) ----------------
#define ATT_SMEM ((3 * 64 * 128 + 64 * 64 + 3 * 64) * 4)

__global__ void __launch_bounds__(256) attn_kernel(const float* __restrict__ qkv,
                                                   float* __restrict__ aout) {
    const int qt = blockIdx.x, h = blockIdx.y, b = blockIdx.z;
    const int kvh = h >> 2;

    extern __shared__ float smf[];
    float* Qs   = smf;
    float* Kst  = Qs + 64 * 128;
    float* Vs   = Kst + 128 * 64;
    float* Ss   = Vs + 64 * 128;
    float* rowm = Ss + 64 * 64;
    float* rowl = rowm + 64;
    float* rowa = rowl + 64;

    const int tid = threadIdx.x;
    const int q0 = qt * 64;

    for (int i = tid; i < 64 * 32; i += 256) {
        int r = i >> 5, c4 = i & 31;
        *(float4*)&Qs[r * 128 + c4 * 4] =
            *(const float4*)(qkv + (size_t)(b * SEQ + q0 + r) * QKV_N + h * HD + c4 * 4);
    }
    if (tid < 64) { rowm[tid] = NEGF; rowl[tid] = 0.0f; }

    const int ty = tid >> 4, tx = tid & 15;
    const int r0 = ty * 4;
    float o[4][8];
#pragma unroll
    for (int a = 0; a < 4; a++)
#pragma unroll
        for (int j = 0; j < 8; j++) o[a][j] = 0.0f;
    __syncthreads();

    const float scale = 0.0883883476483184f;

    for (int kt = 0; kt <= qt; kt++) {
        const int k0 = kt * 64;
        for (int i = tid; i < 2048; i += 256) {
            int r = i & 63, c4 = i >> 6;
            float4 kk = *(const float4*)(qkv + (size_t)(b * SEQ + k0 + r) * QKV_N
                                         + NH * HD + kvh * HD + c4 * 4);
            int d0 = c4 * 4;
            Kst[(d0 + 0) * 64 + r] = kk.x;
            Kst[(d0 + 1) * 64 + r] = kk.y;
            Kst[(d0 + 2) * 64 + r] = kk.z;
            Kst[(d0 + 3) * 64 + r] = kk.w;
        }
        for (int i = tid; i < 2048; i += 256) {
            int r = i >> 5, c4 = i & 31;
            *(float4*)&Vs[r * 128 + c4 * 4] =
                *(const float4*)(qkv + (size_t)(b * SEQ + k0 + r) * QKV_N
                                 + (NH + NKV) * HD + kvh * HD + c4 * 4);
        }
        __syncthreads();

        float s[4][4];
#pragma unroll
        for (int a = 0; a < 4; a++)
#pragma unroll
            for (int j = 0; j < 4; j++) s[a][j] = 0.0f;

#pragma unroll 4
        for (int k = 0; k < 128; k++) {
            float qa[4], kb[4];
#pragma unroll
            for (int a = 0; a < 4; a++) qa[a] = Qs[(r0 + a) * 128 + k];
#pragma unroll
            for (int j = 0; j < 4; j++) kb[j] = Kst[k * 64 + tx * 4 + j];
#pragma unroll
            for (int a = 0; a < 4; a++)
#pragma unroll
                for (int j = 0; j < 4; j++) s[a][j] += qa[a] * kb[j];
        }
        const bool diag = (kt == qt);
#pragma unroll
        for (int a = 0; a < 4; a++)
#pragma unroll
            for (int j = 0; j < 4; j++) {
                float v = s[a][j] * scale;
                if (diag && (r0 + a) < (tx * 4 + j)) v = NEGF;
                Ss[(r0 + a) * 64 + tx * 4 + j] = v;
            }
        __syncthreads();

        {
            const int row = tid >> 2, l4 = tid & 3;
            float mx = NEGF;
            for (int cc = l4; cc < 64; cc += 4) mx = fmaxf(mx, Ss[row * 64 + cc]);
            mx = fmaxf(mx, __shfl_xor_sync(0xffffffffu, mx, 1));
            mx = fmaxf(mx, __shfl_xor_sync(0xffffffffu, mx, 2));
            const float mold = rowm[row];
            const float mnew = fmaxf(mold, mx);
            float ls = 0.0f;
            for (int cc = l4; cc < 64; cc += 4) {
                float p = expf(Ss[row * 64 + cc] - mnew);
                Ss[row * 64 + cc] = p;
                ls += p;
            }
            ls += __shfl_xor_sync(0xffffffffu, ls, 1);
            ls += __shfl_xor_sync(0xffffffffu, ls, 2);
            if (l4 == 0) {
                const float alpha = expf(mold - mnew);
                rowa[row] = alpha;
                rowl[row] = rowl[row] * alpha + ls;
                rowm[row] = mnew;
            }
        }
        __syncthreads();

        float al[4];
#pragma unroll
        for (int a = 0; a < 4; a++) al[a] = rowa[r0 + a];
#pragma unroll
        for (int a = 0; a < 4; a++)
#pragma unroll
            for (int j = 0; j < 8; j++) o[a][j] *= al[a];

#pragma unroll 2
        for (int kk = 0; kk < 64; kk++) {
            float p[4];
#pragma unroll
            for (int a = 0; a < 4; a++) p[a] = Ss[(r0 + a) * 64 + kk];
            float4 v0 = *(const float4*)&Vs[kk * 128 + tx * 8];
            float4 v1 = *(const float4*)&Vs[kk * 128 + tx * 8 + 4];
            float vv[8] = {v0.x, v0.y, v0.z, v0.w, v1.x, v1.y, v1.z, v1.w};
#pragma unroll
            for (int a = 0; a < 4; a++)
#pragma unroll
                for (int j = 0; j < 8; j++) o[a][j] += p[a] * vv[j];
        }
        __syncthreads();
    }

    float il[4];
#pragma unroll
    for (int a = 0; a < 4; a++) il[a] = 1.0f / rowl[r0 + a];
#pragma unroll
    for (int a = 0; a < 4; a++) {
        size_t off = (size_t)(b * SEQ + q0 + r0 + a) * HID + h * HD + tx * 8;
        float4 o0 = make_float4(tfr(o[a][0] * il[a]), tfr(o[a][1] * il[a]),
                                tfr(o[a][2] * il[a]), tfr(o[a][3] * il[a]));
        float4 o1 = make_float4(tfr(o[a][4] * il[a]), tfr(o[a][5] * il[a]),
                                tfr(o[a][6] * il[a]), tfr(o[a][7] * il[a]));
        *(float4*)(aout + off)     = o0;
        *(float4*)(aout + off + 4) = o1;
    }
}

// ---------------- SiLU(gate)*up (output RNA-rounded) ----------------
__global__ void __launch_bounds__(256) silu_kernel(const float* __restrict__ gu,
                                                   float* __restrict__ act) {
    size_t idx = (size_t)blockIdx.x * 256 + threadIdx.x;
    int row = (int)(idx / (FFI / 4));
    int c   = (int)(idx % (FFI / 4));
    const float4 g = *(const float4*)(gu + (size_t)row * 2 * FFI + c * 4);
    const float4 u = *(const float4*)(gu + (size_t)row * 2 * FFI + FFI + c * 4);
    float4 r;
    r.x = tfr(g.x / (1.0f + expf(-g.x)) * u.x);
    r.y = tfr(g.y / (1.0f + expf(-g.y)) * u.y);
    r.z = tfr(g.z / (1.0f + expf(-g.z)) * u.z);
    r.w = tfr(g.w / (1.0f + expf(-g.w)) * u.w);
    *(float4*)(act + (size_t)row * FFI + c * 4) = r;
}

// ---------------- launch ----------------
extern "C" void kernel_launch(void* const* d_in, const int* in_sizes, int n_in,
                              void* d_out, int out_size) {
    const float* x    = (const float*)d_in[0];
    const float* ln1w = (const float*)d_in[1];
    const float* wqkv = (const float*)d_in[2];
    const float* wo   = (const float*)d_in[3];
    const float* ln2w = (const float*)d_in[4];
    const float* wgu  = (const float*)d_in[5];
    const float* wdn  = (const float*)d_in[6];
    const int*   pos  = (const int*)d_in[7];
    float* out = (float*)d_out;

    void *ph, *pqkv, *paout, *ph1, *ph2, *pgu, *pact, *pwq, *pwo, *pwg, *pwd;
    cudaGetSymbolAddress(&ph,    g_h);
    cudaGetSymbolAddress(&pqkv,  g_qkv);
    cudaGetSymbolAddress(&paout, g_aout);
    cudaGetSymbolAddress(&ph1,   g_h1);
    cudaGetSymbolAddress(&ph2,   g_h2);
    cudaGetSymbolAddress(&pgu,   g_gu);
    cudaGetSymbolAddress(&pact,  g_act);
    cudaGetSymbolAddress(&pwq,   g_wqkvR);
    cudaGetSymbolAddress(&pwo,   g_woR);
    cudaGetSymbolAddress(&pwg,   g_wguR);
    cudaGetSymbolAddress(&pwd,   g_wdnR);
    float* h     = (float*)ph;
    float* qkv   = (float*)pqkv;
    float* aout  = (float*)paout;
    float* h1    = (float*)ph1;
    float* h2    = (float*)ph2;
    float* gu    = (float*)pgu;
    float* act   = (float*)pact;
    float* wqkvR = (float*)pwq;
    float* woR   = (float*)pwo;
    float* wguR  = (float*)pwg;
    float* wdnR  = (float*)pwd;

    cudaFuncSetAttribute(attn_kernel, cudaFuncAttributeMaxDynamicSharedMemorySize, ATT_SMEM);

    // 0. RNA-round weights once (tf32-exact bits; GEMM then loads raw)
    roundcopy_kernel<<<(HID * QKV_N / 4) / 256, 256>>>(wqkv, wqkvR);
    roundcopy_kernel<<<(HID * HID / 4) / 256, 256>>>(wo, woR);
    roundcopy_kernel<<<(HID * 2 * FFI / 4) / 256, 256>>>(wgu, wguR);
    roundcopy_kernel<<<(FFI * HID / 4) / 256, 256>>>(wdn, wdnR);

    // 1. h = rmsnorm(x)
    rmsnorm_kernel<<<NT, 256>>>(x, ln1w, h);
    // 2. qkv = h @ wqkv
    tf32gemm_kernel<0><<<dim3(QKV_N / 128, NT / 128), 256>>>(h, wqkvR, nullptr, qkv, NT, QKV_N, HID);
    // 3. rope
    rope_kernel<<<dim3(NT, NH + NKV), 64>>>(qkv, pos);
    // 4. attention
    attn_kernel<<<dim3(SEQ / 64, NH, NB), 256, ATT_SMEM>>>(qkv, aout);
    // 5. h1 = x + aout @ wo
    tf32gemm_kernel<1><<<dim3(HID / 128, NT / 128), 256>>>(aout, woR, x, h1, NT, HID, HID);
    // 6. h2 = rmsnorm(h1)
    rmsnorm_kernel<<<NT, 256>>>(h1, ln2w, h2);
    // 7. gu = h2 @ w_gate_up
    tf32gemm_kernel<0><<<dim3(2 * FFI / 128, NT / 128), 256>>>(h2, wguR, nullptr, gu, NT, 2 * FFI, HID);
    // 8. act = silu(gate)*up
    silu_kernel<<<(NT * FFI / 4) / 256, 256>>>(gu, act);
    // 9. out = h1 + act @ w_down
    tf32gemm_kernel<1><<<dim3(HID / 128, NT / 128), 256>>>(act, wdnR, h1, out, NT, HID, FFI);
}

// round 8
// speedup vs baseline: 2.7937x; 1.7206x over previous
#include <cuda_runtime.h>
#include <cuda_fp16.h>
#include <math.h>
#include <stdint.h>

// Problem constants
#define HID   2048
#define NH    16
#define NKV   4
#define HD    128
#define SEQ   1024
#define NB    4
#define NT    4096
#define QKV_N 3072
#define FFI   8192
#define EPS   1e-6f
#define NEGF  (-1e30f)

// ---------------- scratch ----------------
__device__ __half g_hH   [(size_t)NT * HID];      // rmsnorm1 out (half)
__device__ float  g_qkv  [(size_t)NT * QKV_N];    // qkv (fp32, for rope/attn)
__device__ __half g_aoutH[(size_t)NT * HID];      // attention out (half)
__device__ float  g_h1   [(size_t)NT * HID];      // x + attn@wo (fp32 residual)
__device__ __half g_h2H  [(size_t)NT * HID];      // rmsnorm2 out (half)
__device__ float  g_gu   [(size_t)NT * 2 * FFI];  // gate/up (fp32)
__device__ __half g_actH [(size_t)NT * FFI];      // silu(gate)*up (half)
// fp16 weight copies (same layout as originals)
__device__ __half g_wqkvH[(size_t)HID * QKV_N];
__device__ __half g_woH  [(size_t)HID * HID];
__device__ __half g_wguH [(size_t)HID * 2 * FFI];
__device__ __half g_wdnH [(size_t)FFI * HID];

// ---------------- helpers ----------------
__device__ __forceinline__ void cp_async16(void* s, const void* g) {
    uint32_t sa = (uint32_t)__cvta_generic_to_shared(s);
    asm volatile("cp.async.cg.shared.global [%0], [%1], 16;\n" :: "r"(sa), "l"(g));
}

__device__ __forceinline__ void ldmx4(uint32_t* r, uint32_t a) {
    asm volatile("ldmatrix.sync.aligned.m8n8.x4.shared.b16 {%0,%1,%2,%3}, [%4];"
        : "=r"(r[0]), "=r"(r[1]), "=r"(r[2]), "=r"(r[3]) : "r"(a));
}
__device__ __forceinline__ void ldmx4t(uint32_t* r, uint32_t a) {
    asm volatile("ldmatrix.sync.aligned.m8n8.x4.trans.shared.b16 {%0,%1,%2,%3}, [%4];"
        : "=r"(r[0]), "=r"(r[1]), "=r"(r[2]), "=r"(r[3]) : "r"(a));
}
__device__ __forceinline__ void mma_f16(float* d, const uint32_t* a, const uint32_t* b) {
    asm volatile(
        "mma.sync.aligned.m16n8k16.row.col.f32.f16.f16.f32 "
        "{%0,%1,%2,%3}, {%4,%5,%6,%7}, {%8,%9}, {%0,%1,%2,%3};\n"
        : "+f"(d[0]), "+f"(d[1]), "+f"(d[2]), "+f"(d[3])
        : "r"(a[0]), "r"(a[1]), "r"(a[2]), "r"(a[3]), "r"(b[0]), "r"(b[1]));
}

// ---------------- fp32 -> fp16 weight copy ----------------
__global__ void __launch_bounds__(256) h2fcopy_kernel(const float* __restrict__ s,
                                                      __half* __restrict__ d) {
    const size_t i = ((size_t)blockIdx.x * 256 + threadIdx.x) * 4;
    const float4 v = *(const float4*)(s + i);
    __half2 p0 = __floats2half2_rn(v.x, v.y);
    __half2 p1 = __floats2half2_rn(v.z, v.w);
    uint2 pk = make_uint2(*(uint32_t*)&p0, *(uint32_t*)&p1);
    *(uint2*)(d + i) = pk;
}

// ---------------- FP16 tensor-core GEMM ----------------
// C[M,N] = A[M,K] @ B[K,N] (+R).  Block 128x128, BK=32, 256 threads.
// 8 warps 2x4, warp tile 64x32 = 4x4 m16n8k16 fragments, ldmatrix operand loads.
#define APITCH 40    // halfs; row stride 80B -> ldmatrix banks 20r%32 all-distinct
#define BPITCH 136   // halfs; row stride 272B -> banks 4r%32 all-distinct

template <int EPI>
__global__ void __launch_bounds__(256, 2) f16gemm_kernel(const __half* __restrict__ A,
                                                         const __half* __restrict__ B,
                                                         const float* __restrict__ R,
                                                         float* __restrict__ C,
                                                         int M, int N, int K) {
    __shared__ __half As[2][128 * APITCH];
    __shared__ __half Bs[2][32 * BPITCH];

    const int tid  = threadIdx.x;
    const int bm   = blockIdx.y * 128;
    const int bn   = blockIdx.x * 128;
    const int lane = tid & 31;
    const int warp = tid >> 5;
    const int g = lane >> 2;
    const int c = lane & 3;
    const int wm = (warp >> 2) * 64;
    const int wn = (warp & 3) * 32;

    float acc[4][4][4];
#pragma unroll
    for (int mi = 0; mi < 4; mi++)
#pragma unroll
        for (int ni = 0; ni < 4; ni++)
#pragma unroll
            for (int r = 0; r < 4; r++) acc[mi][ni][r] = 0.0f;

    const int ntiles = K >> 5;

    auto load_tile = [&](int t, int b) {
        const int kof = t << 5;
#pragma unroll
        for (int j = 0; j < 2; j++) {
            const int ca = tid + j * 256;            // A chunks: 512 total
            const int row = ca >> 2, kc = ca & 3;
            cp_async16(&As[b][row * APITCH + kc * 8],
                       A + (size_t)(bm + row) * K + kof + kc * 8);
        }
#pragma unroll
        for (int j = 0; j < 2; j++) {
            const int cb = tid + j * 256;            // B chunks: 512 total
            const int row = cb >> 4, nc = cb & 15;
            cp_async16(&Bs[b][row * BPITCH + nc * 8],
                       B + (size_t)(kof + row) * N + bn + nc * 8);
        }
        asm volatile("cp.async.commit_group;\n");
    };

    load_tile(0, 0);

    // ldmatrix lane address components
    const int aq = lane >> 3;                 // submatrix id 0..3
    const int arow = (lane & 7) + (aq & 1) * 8;
    const int acol = (aq >> 1) * 8;
    const int bkrow = (aq & 1) * 8 + (lane & 7);
    const int bncol = (aq >> 1) * 8;

    for (int t = 0; t < ntiles; t++) {
        const int buf = t & 1;
        if (t + 1 < ntiles) {
            load_tile(t + 1, (t + 1) & 1);
            asm volatile("cp.async.wait_group 1;\n");
        } else {
            asm volatile("cp.async.wait_group 0;\n");
        }
        __syncthreads();

        const uint32_t baseA = (uint32_t)__cvta_generic_to_shared(&As[buf][0]);
        const uint32_t baseB = (uint32_t)__cvta_generic_to_shared(&Bs[buf][0]);

#pragma unroll
        for (int ks = 0; ks < 2; ks++) {
            const int k0 = ks << 4;
            uint32_t af[4][4], bf[2][4];
#pragma unroll
            for (int mi = 0; mi < 4; mi++) {
                const int row = wm + mi * 16 + arow;
                ldmx4(af[mi], baseA + (uint32_t)(row * APITCH + k0 + acol) * 2);
            }
#pragma unroll
            for (int n2 = 0; n2 < 2; n2++) {
                const int kk = k0 + bkrow;
                const int nn = wn + n2 * 16 + bncol;
                ldmx4t(bf[n2], baseB + (uint32_t)(kk * BPITCH + nn) * 2);
            }
#pragma unroll
            for (int mi = 0; mi < 4; mi++)
#pragma unroll
                for (int ni = 0; ni < 4; ni++)
                    mma_f16(acc[mi][ni], af[mi], &bf[ni >> 1][(ni & 1) * 2]);
        }
        __syncthreads();
    }

    // epilogue (fp32 out, optional residual)
#pragma unroll
    for (int mi = 0; mi < 4; mi++) {
#pragma unroll
        for (int ni = 0; ni < 4; ni++) {
            const int row = bm + wm + mi * 16 + g;
            const int col = bn + wn + ni * 8 + 2 * c;
            const size_t o0 = (size_t)row * N + col;
            const size_t o1 = (size_t)(row + 8) * N + col;
            float2 v0 = make_float2(acc[mi][ni][0], acc[mi][ni][1]);
            float2 v1 = make_float2(acc[mi][ni][2], acc[mi][ni][3]);
            if (EPI == 1) {
                float2 r0 = *(const float2*)(R + o0);
                float2 r1 = *(const float2*)(R + o1);
                v0.x += r0.x; v0.y += r0.y;
                v1.x += r1.x; v1.y += r1.y;
            }
            *(float2*)(C + o0) = v0;
            *(float2*)(C + o1) = v1;
        }
    }
}

// ---------------- RMSNorm (fp32 in, half out) ----------------
__global__ void __launch_bounds__(256) rmsnorm_kernel(const float* __restrict__ x,
                                                      const float* __restrict__ w,
                                                      __half* __restrict__ out) {
    const int row = blockIdx.x;
    const int tid = threadIdx.x;
    const float4* xr = (const float4*)(x + (size_t)row * HID);
    const float4* wr = (const float4*)w;

    float4 v0 = xr[tid];
    float4 v1 = xr[tid + 256];
    float ss = v0.x*v0.x + v0.y*v0.y + v0.z*v0.z + v0.w*v0.w
             + v1.x*v1.x + v1.y*v1.y + v1.z*v1.z + v1.w*v1.w;

    __shared__ float red[256];
    red[tid] = ss;
    __syncthreads();
    for (int s = 128; s > 0; s >>= 1) {
        if (tid < s) red[tid] += red[tid + s];
        __syncthreads();
    }
    const float inv = rsqrtf(red[0] * (1.0f / HID) + EPS);

    float4 w0 = wr[tid], w1 = wr[tid + 256];
    __half2* oh = (__half2*)(out + (size_t)row * HID);
    __half2 a0 = __floats2half2_rn(v0.x*inv*w0.x, v0.y*inv*w0.y);
    __half2 a1 = __floats2half2_rn(v0.z*inv*w0.z, v0.w*inv*w0.w);
    __half2 b0 = __floats2half2_rn(v1.x*inv*w1.x, v1.y*inv*w1.y);
    __half2 b1 = __floats2half2_rn(v1.z*inv*w1.z, v1.w*inv*w1.w);
    oh[tid * 2]       = a0;
    oh[tid * 2 + 1]   = a1;
    oh[512 + tid * 2] = b0;
    oh[512 + tid * 2 + 1] = b1;
}

// ---------------- RoPE ----------------
__global__ void rope_kernel(float* __restrict__ qkv, const int* __restrict__ pos) {
    const int t  = blockIdx.x;
    const int hh = blockIdx.y;
    const int i  = threadIdx.x;
    const float p = (float)pos[t & (SEQ - 1)];
    const float inv_freq = powf(10000.0f, -((float)i) / 64.0f);
    float sn, cs;
    sincosf(p * inv_freq, &sn, &cs);
    float* vp = qkv + (size_t)t * QKV_N + hh * HD;
    const float t1 = vp[i];
    const float t2 = vp[i + 64];
    vp[i]      = t1 * cs - t2 * sn;
    vp[i + 64] = t2 * cs + t1 * sn;
}

// ---------------- Flash attention (fp32, causal, GQA; half out) ----------------
#define ATT_SMEM ((3 * 64 * 128 + 64 * 64 + 3 * 64) * 4)

__global__ void __launch_bounds__(256) attn_kernel(const float* __restrict__ qkv,
                                                   __half* __restrict__ aout) {
    const int qt = blockIdx.x, h = blockIdx.y, b = blockIdx.z;
    const int kvh = h >> 2;

    extern __shared__ float smf[];
    float* Qs   = smf;
    float* Kst  = Qs + 64 * 128;
    float* Vs   = Kst + 128 * 64;
    float* Ss   = Vs + 64 * 128;
    float* rowm = Ss + 64 * 64;
    float* rowl = rowm + 64;
    float* rowa = rowl + 64;

    const int tid = threadIdx.x;
    const int q0 = qt * 64;

    for (int i = tid; i < 64 * 32; i += 256) {
        int r = i >> 5, c4 = i & 31;
        *(float4*)&Qs[r * 128 + c4 * 4] =
            *(const float4*)(qkv + (size_t)(b * SEQ + q0 + r) * QKV_N + h * HD + c4 * 4);
    }
    if (tid < 64) { rowm[tid] = NEGF; rowl[tid] = 0.0f; }

    const int ty = tid >> 4, tx = tid & 15;
    const int r0 = ty * 4;
    float o[4][8];
#pragma unroll
    for (int a = 0; a < 4; a++)
#pragma unroll
        for (int j = 0; j < 8; j++) o[a][j] = 0.0f;
    __syncthreads();

    const float scale = 0.0883883476483184f;

    for (int kt = 0; kt <= qt; kt++) {
        const int k0 = kt * 64;
        for (int i = tid; i < 2048; i += 256) {
            int r = i & 63, c4 = i >> 6;
            float4 kk = *(const float4*)(qkv + (size_t)(b * SEQ + k0 + r) * QKV_N
                                         + NH * HD + kvh * HD + c4 * 4);
            int d0 = c4 * 4;
            Kst[(d0 + 0) * 64 + r] = kk.x;
            Kst[(d0 + 1) * 64 + r] = kk.y;
            Kst[(d0 + 2) * 64 + r] = kk.z;
            Kst[(d0 + 3) * 64 + r] = kk.w;
        }
        for (int i = tid; i < 2048; i += 256) {
            int r = i >> 5, c4 = i & 31;
            *(float4*)&Vs[r * 128 + c4 * 4] =
                *(const float4*)(qkv + (size_t)(b * SEQ + k0 + r) * QKV_N
                                 + (NH + NKV) * HD + kvh * HD + c4 * 4);
        }
        __syncthreads();

        float s[4][4];
#pragma unroll
        for (int a = 0; a < 4; a++)
#pragma unroll
            for (int j = 0; j < 4; j++) s[a][j] = 0.0f;

#pragma unroll 4
        for (int k = 0; k < 128; k++) {
            float qa[4], kb[4];
#pragma unroll
            for (int a = 0; a < 4; a++) qa[a] = Qs[(r0 + a) * 128 + k];
#pragma unroll
            for (int j = 0; j < 4; j++) kb[j] = Kst[k * 64 + tx * 4 + j];
#pragma unroll
            for (int a = 0; a < 4; a++)
#pragma unroll
                for (int j = 0; j < 4; j++) s[a][j] += qa[a] * kb[j];
        }
        const bool diag = (kt == qt);
#pragma unroll
        for (int a = 0; a < 4; a++)
#pragma unroll
            for (int j = 0; j < 4; j++) {
                float v = s[a][j] * scale;
                if (diag && (r0 + a) < (tx * 4 + j)) v = NEGF;
                Ss[(r0 + a) * 64 + tx * 4 + j] = v;
            }
        __syncthreads();

        {
            const int row = tid >> 2, l4 = tid & 3;
            float mx = NEGF;
            for (int cc = l4; cc < 64; cc += 4) mx = fmaxf(mx, Ss[row * 64 + cc]);
            mx = fmaxf(mx, __shfl_xor_sync(0xffffffffu, mx, 1));
            mx = fmaxf(mx, __shfl_xor_sync(0xffffffffu, mx, 2));
            const float mold = rowm[row];
            const float mnew = fmaxf(mold, mx);
            float ls = 0.0f;
            for (int cc = l4; cc < 64; cc += 4) {
                float p = expf(Ss[row * 64 + cc] - mnew);
                Ss[row * 64 + cc] = p;
                ls += p;
            }
            ls += __shfl_xor_sync(0xffffffffu, ls, 1);
            ls += __shfl_xor_sync(0xffffffffu, ls, 2);
            if (l4 == 0) {
                const float alpha = expf(mold - mnew);
                rowa[row] = alpha;
                rowl[row] = rowl[row] * alpha + ls;
                rowm[row] = mnew;
            }
        }
        __syncthreads();

        float al[4];
#pragma unroll
        for (int a = 0; a < 4; a++) al[a] = rowa[r0 + a];
#pragma unroll
        for (int a = 0; a < 4; a++)
#pragma unroll
            for (int j = 0; j < 8; j++) o[a][j] *= al[a];

#pragma unroll 2
        for (int kk = 0; kk < 64; kk++) {
            float p[4];
#pragma unroll
            for (int a = 0; a < 4; a++) p[a] = Ss[(r0 + a) * 64 + kk];
            float4 v0 = *(const float4*)&Vs[kk * 128 + tx * 8];
            float4 v1 = *(const float4*)&Vs[kk * 128 + tx * 8 + 4];
            float vv[8] = {v0.x, v0.y, v0.z, v0.w, v1.x, v1.y, v1.z, v1.w};
#pragma unroll
            for (int a = 0; a < 4; a++)
#pragma unroll
                for (int j = 0; j < 8; j++) o[a][j] += p[a] * vv[j];
        }
        __syncthreads();
    }

    float il[4];
#pragma unroll
    for (int a = 0; a < 4; a++) il[a] = 1.0f / rowl[r0 + a];
#pragma unroll
    for (int a = 0; a < 4; a++) {
        size_t off = (size_t)(b * SEQ + q0 + r0 + a) * HID + h * HD + tx * 8;
        __half2* ao = (__half2*)(aout + off);
        ao[0] = __floats2half2_rn(o[a][0] * il[a], o[a][1] * il[a]);
        ao[1] = __floats2half2_rn(o[a][2] * il[a], o[a][3] * il[a]);
        ao[2] = __floats2half2_rn(o[a][4] * il[a], o[a][5] * il[a]);
        ao[3] = __floats2half2_rn(o[a][6] * il[a], o[a][7] * il[a]);
    }
}

// ---------------- SiLU(gate)*up (fp32 in, half out) ----------------
__global__ void __launch_bounds__(256) silu_kernel(const float* __restrict__ gu,
                                                   __half* __restrict__ act) {
    size_t idx = (size_t)blockIdx.x * 256 + threadIdx.x;
    int row = (int)(idx / (FFI / 4));
    int c   = (int)(idx % (FFI / 4));
    const float4 g = *(const float4*)(gu + (size_t)row * 2 * FFI + c * 4);
    const float4 u = *(const float4*)(gu + (size_t)row * 2 * FFI + FFI + c * 4);
    float rx = g.x / (1.0f + expf(-g.x)) * u.x;
    float ry = g.y / (1.0f + expf(-g.y)) * u.y;
    float rz = g.z / (1.0f + expf(-g.z)) * u.z;
    float rw = g.w / (1.0f + expf(-g.w)) * u.w;
    __half2 p0 = __floats2half2_rn(rx, ry);
    __half2 p1 = __floats2half2_rn(rz, rw);
    uint2 pk = make_uint2(*(uint32_t*)&p0, *(uint32_t*)&p1);
    *(uint2*)(act + (size_t)row * FFI + c * 4) = pk;
}

// ---------------- launch ----------------
extern "C" void kernel_launch(void* const* d_in, const int* in_sizes, int n_in,
                              void* d_out, int out_size) {
    const float* x    = (const float*)d_in[0];
    const float* ln1w = (const float*)d_in[1];
    const float* wqkv = (const float*)d_in[2];
    const float* wo   = (const float*)d_in[3];
    const float* ln2w = (const float*)d_in[4];
    const float* wgu  = (const float*)d_in[5];
    const float* wdn  = (const float*)d_in[6];
    const int*   pos  = (const int*)d_in[7];
    float* out = (float*)d_out;

    void *phH, *pqkv, *paoH, *ph1, *ph2H, *pgu, *pactH, *pwq, *pwo, *pwg, *pwd;
    cudaGetSymbolAddress(&phH,   g_hH);
    cudaGetSymbolAddress(&pqkv,  g_qkv);
    cudaGetSymbolAddress(&paoH,  g_aoutH);
    cudaGetSymbolAddress(&ph1,   g_h1);
    cudaGetSymbolAddress(&ph2H,  g_h2H);
    cudaGetSymbolAddress(&pgu,   g_gu);
    cudaGetSymbolAddress(&pactH, g_actH);
    cudaGetSymbolAddress(&pwq,   g_wqkvH);
    cudaGetSymbolAddress(&pwo,   g_woH);
    cudaGetSymbolAddress(&pwg,   g_wguH);
    cudaGetSymbolAddress(&pwd,   g_wdnH);
    __half* hH    = (__half*)phH;
    float*  qkv   = (float*)pqkv;
    __half* aoutH = (__half*)paoH;
    float*  h1    = (float*)ph1;
    __half* h2H   = (__half*)ph2H;
    float*  gu    = (float*)pgu;
    __half* actH  = (__half*)pactH;
    __half* wqkvH = (__half*)pwq;
    __half* woH   = (__half*)pwo;
    __half* wguH  = (__half*)pwg;
    __half* wdnH  = (__half*)pwd;

    cudaFuncSetAttribute(attn_kernel, cudaFuncAttributeMaxDynamicSharedMemorySize, ATT_SMEM);

    // 0. convert weights to fp16 once
    h2fcopy_kernel<<<(HID * QKV_N / 4) / 256, 256>>>(wqkv, wqkvH);
    h2fcopy_kernel<<<(HID * HID / 4) / 256, 256>>>(wo, woH);
    h2fcopy_kernel<<<(HID * 2 * FFI / 4) / 256, 256>>>(wgu, wguH);
    h2fcopy_kernel<<<(FFI * HID / 4) / 256, 256>>>(wdn, wdnH);

    // 1. h = rmsnorm(x) -> half
    rmsnorm_kernel<<<NT, 256>>>(x, ln1w, hH);
    // 2. qkv = h @ wqkv  (fp16 mma, fp32 out)
    f16gemm_kernel<0><<<dim3(QKV_N / 128, NT / 128), 256>>>(hH, wqkvH, nullptr, qkv, NT, QKV_N, HID);
    // 3. rope
    rope_kernel<<<dim3(NT, NH + NKV), 64>>>(qkv, pos);
    // 4. attention -> half aout
    attn_kernel<<<dim3(SEQ / 64, NH, NB), 256, ATT_SMEM>>>(qkv, aoutH);
    // 5. h1 = x + aout @ wo
    f16gemm_kernel<1><<<dim3(HID / 128, NT / 128), 256>>>(aoutH, woH, x, h1, NT, HID, HID);
    // 6. h2 = rmsnorm(h1) -> half
    rmsnorm_kernel<<<NT, 256>>>(h1, ln2w, h2H);
    // 7. gu = h2 @ w_gate_up
    f16gemm_kernel<0><<<dim3(2 * FFI / 128, NT / 128), 256>>>(h2H, wguH, nullptr, gu, NT, 2 * FFI, HID);
    // 8. act = silu(gate)*up -> half
    silu_kernel<<<(NT * FFI / 4) / 256, 256>>>(gu, actH);
    // 9. out = h1 + act @ w_down
    f16gemm_kernel<1><<<dim3(HID / 128, NT / 128), 256>>>(actH, wdnH, h1, out, NT, HID, FFI);
}

// round 9
// speedup vs baseline: 3.5490x; 1.2704x over previous
#include <cuda_runtime.h>
#include <cuda_fp16.h>
#include <math.h>
#include <stdint.h>

// Problem constants
#define HID   2048
#define NH    16
#define NKV   4
#define HD    128
#define SEQ   1024
#define NB    4
#define NT    4096
#define QKV_N 3072
#define FFI   8192
#define EPS   1e-6f
#define NEGF  (-1e30f)

// ---------------- scratch ----------------
__device__ __half g_hH   [(size_t)NT * HID];
__device__ float  g_qkv  [(size_t)NT * QKV_N];
__device__ __half g_aoutH[(size_t)NT * HID];
__device__ float  g_h1   [(size_t)NT * HID];
__device__ __half g_h2H  [(size_t)NT * HID];
__device__ float  g_gu   [(size_t)NT * 2 * FFI];
__device__ __half g_actH [(size_t)NT * FFI];
__device__ __half g_wqkvH[(size_t)HID * QKV_N];
__device__ __half g_woH  [(size_t)HID * HID];
__device__ __half g_wguH [(size_t)HID * 2 * FFI];
__device__ __half g_wdnH [(size_t)FFI * HID];

// ---------------- helpers ----------------
__device__ __forceinline__ void cp_async16(void* s, const void* g) {
    uint32_t sa = (uint32_t)__cvta_generic_to_shared(s);
    asm volatile("cp.async.cg.shared.global [%0], [%1], 16;\n" :: "r"(sa), "l"(g));
}
__device__ __forceinline__ void ldmx4(uint32_t* r, uint32_t a) {
    asm volatile("ldmatrix.sync.aligned.m8n8.x4.shared.b16 {%0,%1,%2,%3}, [%4];"
        : "=r"(r[0]), "=r"(r[1]), "=r"(r[2]), "=r"(r[3]) : "r"(a));
}
__device__ __forceinline__ void ldmx4t(uint32_t* r, uint32_t a) {
    asm volatile("ldmatrix.sync.aligned.m8n8.x4.trans.shared.b16 {%0,%1,%2,%3}, [%4];"
        : "=r"(r[0]), "=r"(r[1]), "=r"(r[2]), "=r"(r[3]) : "r"(a));
}
__device__ __forceinline__ void mma_f16(float* d, const uint32_t* a, const uint32_t* b) {
    asm volatile(
        "mma.sync.aligned.m16n8k16.row.col.f32.f16.f16.f32 "
        "{%0,%1,%2,%3}, {%4,%5,%6,%7}, {%8,%9}, {%0,%1,%2,%3};\n"
        : "+f"(d[0]), "+f"(d[1]), "+f"(d[2]), "+f"(d[3])
        : "r"(a[0]), "r"(a[1]), "r"(a[2]), "r"(a[3]), "r"(b[0]), "r"(b[1]));
}

// ---------------- fp32 -> fp16 weight copy ----------------
__global__ void __launch_bounds__(256) h2fcopy_kernel(const float* __restrict__ s,
                                                      __half* __restrict__ d) {
    const size_t i = ((size_t)blockIdx.x * 256 + threadIdx.x) * 4;
    const float4 v = *(const float4*)(s + i);
    __half2 p0 = __floats2half2_rn(v.x, v.y);
    __half2 p1 = __floats2half2_rn(v.z, v.w);
    uint2 pk = make_uint2(*(uint32_t*)&p0, *(uint32_t*)&p1);
    *(uint2*)(d + i) = pk;
}

// ---------------- FP16 tensor-core GEMM (unchanged from round 8) ----------------
#define APITCH 40
#define BPITCH 136

template <int EPI>
__global__ void __launch_bounds__(256, 2) f16gemm_kernel(const __half* __restrict__ A,
                                                         const __half* __restrict__ B,
                                                         const float* __restrict__ R,
                                                         float* __restrict__ C,
                                                         int M, int N, int K) {
    __shared__ __half As[2][128 * APITCH];
    __shared__ __half Bs[2][32 * BPITCH];

    const int tid  = threadIdx.x;
    const int bm   = blockIdx.y * 128;
    const int bn   = blockIdx.x * 128;
    const int lane = tid & 31;
    const int warp = tid >> 5;
    const int g = lane >> 2;
    const int c = lane & 3;
    const int wm = (warp >> 2) * 64;
    const int wn = (warp & 3) * 32;

    float acc[4][4][4];
#pragma unroll
    for (int mi = 0; mi < 4; mi++)
#pragma unroll
        for (int ni = 0; ni < 4; ni++)
#pragma unroll
            for (int r = 0; r < 4; r++) acc[mi][ni][r] = 0.0f;

    const int ntiles = K >> 5;

    auto load_tile = [&](int t, int b) {
        const int kof = t << 5;
#pragma unroll
        for (int j = 0; j < 2; j++) {
            const int ca = tid + j * 256;
            const int row = ca >> 2, kc = ca & 3;
            cp_async16(&As[b][row * APITCH + kc * 8],
                       A + (size_t)(bm + row) * K + kof + kc * 8);
        }
#pragma unroll
        for (int j = 0; j < 2; j++) {
            const int cb = tid + j * 256;
            const int row = cb >> 4, nc = cb & 15;
            cp_async16(&Bs[b][row * BPITCH + nc * 8],
                       B + (size_t)(kof + row) * N + bn + nc * 8);
        }
        asm volatile("cp.async.commit_group;\n");
    };

    load_tile(0, 0);

    const int aq = lane >> 3;
    const int arow = (lane & 7) + (aq & 1) * 8;
    const int acol = (aq >> 1) * 8;
    const int bkrow = (aq & 1) * 8 + (lane & 7);
    const int bncol = (aq >> 1) * 8;

    for (int t = 0; t < ntiles; t++) {
        const int buf = t & 1;
        if (t + 1 < ntiles) {
            load_tile(t + 1, (t + 1) & 1);
            asm volatile("cp.async.wait_group 1;\n");
        } else {
            asm volatile("cp.async.wait_group 0;\n");
        }
        __syncthreads();

        const uint32_t baseA = (uint32_t)__cvta_generic_to_shared(&As[buf][0]);
        const uint32_t baseB = (uint32_t)__cvta_generic_to_shared(&Bs[buf][0]);

#pragma unroll
        for (int ks = 0; ks < 2; ks++) {
            const int k0 = ks << 4;
            uint32_t af[4][4], bf[2][4];
#pragma unroll
            for (int mi = 0; mi < 4; mi++) {
                const int row = wm + mi * 16 + arow;
                ldmx4(af[mi], baseA + (uint32_t)(row * APITCH + k0 + acol) * 2);
            }
#pragma unroll
            for (int n2 = 0; n2 < 2; n2++) {
                const int kk = k0 + bkrow;
                const int nn = wn + n2 * 16 + bncol;
                ldmx4t(bf[n2], baseB + (uint32_t)(kk * BPITCH + nn) * 2);
            }
#pragma unroll
            for (int mi = 0; mi < 4; mi++)
#pragma unroll
                for (int ni = 0; ni < 4; ni++)
                    mma_f16(acc[mi][ni], af[mi], &bf[ni >> 1][(ni & 1) * 2]);
        }
        __syncthreads();
    }

#pragma unroll
    for (int mi = 0; mi < 4; mi++) {
#pragma unroll
        for (int ni = 0; ni < 4; ni++) {
            const int row = bm + wm + mi * 16 + g;
            const int col = bn + wn + ni * 8 + 2 * c;
            const size_t o0 = (size_t)row * N + col;
            const size_t o1 = (size_t)(row + 8) * N + col;
            float2 v0 = make_float2(acc[mi][ni][0], acc[mi][ni][1]);
            float2 v1 = make_float2(acc[mi][ni][2], acc[mi][ni][3]);
            if (EPI == 1) {
                float2 r0 = *(const float2*)(R + o0);
                float2 r1 = *(const float2*)(R + o1);
                v0.x += r0.x; v0.y += r0.y;
                v1.x += r1.x; v1.y += r1.y;
            }
            *(float2*)(C + o0) = v0;
            *(float2*)(C + o1) = v1;
        }
    }
}

// ---------------- RMSNorm (fp32 in, half out) ----------------
__global__ void __launch_bounds__(256) rmsnorm_kernel(const float* __restrict__ x,
                                                      const float* __restrict__ w,
                                                      __half* __restrict__ out) {
    const int row = blockIdx.x;
    const int tid = threadIdx.x;
    const float4* xr = (const float4*)(x + (size_t)row * HID);
    const float4* wr = (const float4*)w;

    float4 v0 = xr[tid];
    float4 v1 = xr[tid + 256];
    float ss = v0.x*v0.x + v0.y*v0.y + v0.z*v0.z + v0.w*v0.w
             + v1.x*v1.x + v1.y*v1.y + v1.z*v1.z + v1.w*v1.w;

    __shared__ float red[256];
    red[tid] = ss;
    __syncthreads();
    for (int s = 128; s > 0; s >>= 1) {
        if (tid < s) red[tid] += red[tid + s];
        __syncthreads();
    }
    const float inv = rsqrtf(red[0] * (1.0f / HID) + EPS);

    float4 w0 = wr[tid], w1 = wr[tid + 256];
    __half2* oh = (__half2*)(out + (size_t)row * HID);
    __half2 a0 = __floats2half2_rn(v0.x*inv*w0.x, v0.y*inv*w0.y);
    __half2 a1 = __floats2half2_rn(v0.z*inv*w0.z, v0.w*inv*w0.w);
    __half2 b0 = __floats2half2_rn(v1.x*inv*w1.x, v1.y*inv*w1.y);
    __half2 b1 = __floats2half2_rn(v1.z*inv*w1.z, v1.w*inv*w1.w);
    oh[tid * 2]       = a0;
    oh[tid * 2 + 1]   = a1;
    oh[512 + tid * 2] = b0;
    oh[512 + tid * 2 + 1] = b1;
}

// ---------------- RoPE ----------------
__global__ void rope_kernel(float* __restrict__ qkv, const int* __restrict__ pos) {
    const int t  = blockIdx.x;
    const int hh = blockIdx.y;
    const int i  = threadIdx.x;
    const float p = (float)pos[t & (SEQ - 1)];
    const float inv_freq = powf(10000.0f, -((float)i) / 64.0f);
    float sn, cs;
    sincosf(p * inv_freq, &sn, &cs);
    float* vp = qkv + (size_t)t * QKV_N + hh * HD;
    const float t1 = vp[i];
    const float t2 = vp[i + 64];
    vp[i]      = t1 * cs - t2 * sn;
    vp[i + 64] = t2 * cs + t1 * sn;
}

// ---------------- Flash attention (fp16 tensor-core, fp32 softmax) ----------------
// BM=64, BN=64, D=128.  8 warps: warp (wr=w>>1, wc=w&1).
// S-phase: warp computes rows wr*16..+16, cols wc*32..+32.
// O-phase: warp computes rows wr*16..+16, cols wc*64..+64.
#define QP 136   // Q pitch (halfs)
#define KP 72    // K^T pitch
#define VP 136   // V pitch
#define PP 72    // P pitch
#define ATT_SMEM ((64*QP + 128*KP + 64*VP + 64*PP) * 2 + (64*64 + 3*64) * 4)

__global__ void __launch_bounds__(256) attn_kernel(const float* __restrict__ qkv,
                                                   __half* __restrict__ aout) {
    const int qt = blockIdx.x, h = blockIdx.y, b = blockIdx.z;
    const int kvh = h >> 2;

    extern __shared__ char smb[];
    __half* Qh = (__half*)smb;          // [64][QP]
    __half* Kh = Qh + 64 * QP;          // [128][KP]  (d-major: [k][n])
    __half* Vh = Kh + 128 * KP;         // [64][VP]   ([kv][d])
    __half* Ph = Vh + 64 * VP;          // [64][PP]
    float* Ss   = (float*)(Ph + 64 * PP);  // [64][64]
    float* rowm = Ss + 64 * 64;
    float* rowl = rowm + 64;
    float* rowa = rowl + 64;

    const int tid  = threadIdx.x;
    const int lane = tid & 31;
    const int warp = tid >> 5;
    const int wr = warp >> 1, wc = warp & 1;
    const int g = lane >> 2, c = lane & 3;
    const int aq = lane >> 3;
    const int arow = (lane & 7) + (aq & 1) * 8;
    const int acol = (aq >> 1) * 8;
    const int bkrow = (aq & 1) * 8 + (lane & 7);
    const int bncol = (aq >> 1) * 8;
    const int q0 = qt * 64;

    const uint32_t baseQ = (uint32_t)__cvta_generic_to_shared(Qh);
    const uint32_t baseK = (uint32_t)__cvta_generic_to_shared(Kh);
    const uint32_t baseV = (uint32_t)__cvta_generic_to_shared(Vh);
    const uint32_t baseP = (uint32_t)__cvta_generic_to_shared(Ph);

    // load Q tile (fp32 -> half)
    for (int i = tid; i < 64 * 32; i += 256) {
        const int r = i >> 5, c4 = i & 31;
        float4 q = *(const float4*)(qkv + (size_t)(b * SEQ + q0 + r) * QKV_N + h * HD + c4 * 4);
        __half2 p0 = __floats2half2_rn(q.x, q.y);
        __half2 p1 = __floats2half2_rn(q.z, q.w);
        *(uint2*)&Qh[r * QP + c4 * 4] = make_uint2(*(uint32_t*)&p0, *(uint32_t*)&p1);
    }
    if (tid < 64) { rowm[tid] = NEGF; rowl[tid] = 0.0f; }

    float oacc[8][4];
#pragma unroll
    for (int ni = 0; ni < 8; ni++)
#pragma unroll
        for (int r = 0; r < 4; r++) oacc[ni][r] = 0.0f;
    __syncthreads();

    const float scale = 0.0883883476483184f;

    for (int kt = 0; kt <= qt; kt++) {
        const int k0 = kt * 64;
        // K tile: transpose to [d][n] halfs
        for (int i = tid; i < 2048; i += 256) {
            const int r = i & 63, c4 = i >> 6;
            float4 kk = *(const float4*)(qkv + (size_t)(b * SEQ + k0 + r) * QKV_N
                                         + NH * HD + kvh * HD + c4 * 4);
            const int d0 = c4 * 4;
            Kh[(d0 + 0) * KP + r] = __float2half_rn(kk.x);
            Kh[(d0 + 1) * KP + r] = __float2half_rn(kk.y);
            Kh[(d0 + 2) * KP + r] = __float2half_rn(kk.z);
            Kh[(d0 + 3) * KP + r] = __float2half_rn(kk.w);
        }
        // V tile: [kv][d] halfs
        for (int i = tid; i < 2048; i += 256) {
            const int r = i >> 5, c4 = i & 31;
            float4 vv = *(const float4*)(qkv + (size_t)(b * SEQ + k0 + r) * QKV_N
                                         + (NH + NKV) * HD + kvh * HD + c4 * 4);
            __half2 p0 = __floats2half2_rn(vv.x, vv.y);
            __half2 p1 = __floats2half2_rn(vv.z, vv.w);
            *(uint2*)&Vh[r * VP + c4 * 4] = make_uint2(*(uint32_t*)&p0, *(uint32_t*)&p1);
        }
        __syncthreads();

        // S = Q @ K^T  (warp: rows wr*16..+16, cols wc*32..+32)
        float sacc[4][4];
#pragma unroll
        for (int ni = 0; ni < 4; ni++)
#pragma unroll
            for (int r = 0; r < 4; r++) sacc[ni][r] = 0.0f;

#pragma unroll
        for (int k16 = 0; k16 < 8; k16++) {
            uint32_t af[4], bf[2][4];
            ldmx4(af, baseQ + (uint32_t)((wr * 16 + arow) * QP + k16 * 16 + acol) * 2);
#pragma unroll
            for (int n2 = 0; n2 < 2; n2++)
                ldmx4t(bf[n2], baseK + (uint32_t)((k16 * 16 + bkrow) * KP
                                                  + wc * 32 + n2 * 16 + bncol) * 2);
#pragma unroll
            for (int ni = 0; ni < 4; ni++)
                mma_f16(sacc[ni], af, &bf[ni >> 1][(ni & 1) * 2]);
        }

        // write scores (scale + causal mask)
        const bool diag = (kt == qt);
        const int srow0 = wr * 16 + g;
#pragma unroll
        for (int ni = 0; ni < 4; ni++) {
            const int col = wc * 32 + ni * 8 + 2 * c;
            float v0 = sacc[ni][0] * scale;
            float v1 = sacc[ni][1] * scale;
            float v2 = sacc[ni][2] * scale;
            float v3 = sacc[ni][3] * scale;
            if (diag) {
                if (srow0 < col)           v0 = NEGF;
                if (srow0 < col + 1)       v1 = NEGF;
                if (srow0 + 8 < col)       v2 = NEGF;
                if (srow0 + 8 < col + 1)   v3 = NEGF;
            }
            Ss[srow0 * 64 + col]           = v0;
            Ss[srow0 * 64 + col + 1]       = v1;
            Ss[(srow0 + 8) * 64 + col]     = v2;
            Ss[(srow0 + 8) * 64 + col + 1] = v3;
        }
        __syncthreads();

        // online softmax (4 threads per row)
        {
            const int row = tid >> 2, l4 = tid & 3;
            float mx = NEGF;
            for (int cc = l4; cc < 64; cc += 4) mx = fmaxf(mx, Ss[row * 64 + cc]);
            mx = fmaxf(mx, __shfl_xor_sync(0xffffffffu, mx, 1));
            mx = fmaxf(mx, __shfl_xor_sync(0xffffffffu, mx, 2));
            const float mold = rowm[row];
            const float mnew = fmaxf(mold, mx);
            float ls = 0.0f;
            for (int cc = l4; cc < 64; cc += 4) {
                float p = expf(Ss[row * 64 + cc] - mnew);
                Ss[row * 64 + cc] = p;
                ls += p;
            }
            ls += __shfl_xor_sync(0xffffffffu, ls, 1);
            ls += __shfl_xor_sync(0xffffffffu, ls, 2);
            if (l4 == 0) {
                const float alpha = expf(mold - mnew);
                rowa[row] = alpha;
                rowl[row] = rowl[row] * alpha + ls;
                rowm[row] = mnew;
            }
        }
        __syncthreads();

        // convert probs to half + rescale O accumulators
        {
            const int row = tid >> 2, c0 = (tid & 3) * 16;
#pragma unroll
            for (int j = 0; j < 8; j++) {
                __half2 p = __floats2half2_rn(Ss[row * 64 + c0 + 2 * j],
                                              Ss[row * 64 + c0 + 2 * j + 1]);
                *(__half2*)&Ph[row * PP + c0 + 2 * j] = p;
            }
        }
        const float al0 = rowa[wr * 16 + g];
        const float al1 = rowa[wr * 16 + g + 8];
#pragma unroll
        for (int ni = 0; ni < 8; ni++) {
            oacc[ni][0] *= al0; oacc[ni][1] *= al0;
            oacc[ni][2] *= al1; oacc[ni][3] *= al1;
        }
        __syncthreads();

        // O += P @ V  (warp: rows wr*16..+16, cols wc*64..+64)
#pragma unroll
        for (int k16 = 0; k16 < 4; k16++) {
            uint32_t af[4], bf[4][4];
            ldmx4(af, baseP + (uint32_t)((wr * 16 + arow) * PP + k16 * 16 + acol) * 2);
#pragma unroll
            for (int n2 = 0; n2 < 4; n2++)
                ldmx4t(bf[n2], baseV + (uint32_t)((k16 * 16 + bkrow) * VP
                                                  + wc * 64 + n2 * 16 + bncol) * 2);
#pragma unroll
            for (int ni = 0; ni < 8; ni++)
                mma_f16(oacc[ni], af, &bf[ni >> 1][(ni & 1) * 2]);
        }
        __syncthreads();
    }

    // normalize & write (half out)
    const float il0 = 1.0f / rowl[wr * 16 + g];
    const float il1 = 1.0f / rowl[wr * 16 + g + 8];
    const size_t r0g = (size_t)(b * SEQ + q0 + wr * 16 + g) * HID + h * HD;
    const size_t r1g = (size_t)(b * SEQ + q0 + wr * 16 + g + 8) * HID + h * HD;
#pragma unroll
    for (int ni = 0; ni < 8; ni++) {
        const int col = wc * 64 + ni * 8 + 2 * c;
        __half2 p0 = __floats2half2_rn(oacc[ni][0] * il0, oacc[ni][1] * il0);
        __half2 p1 = __floats2half2_rn(oacc[ni][2] * il1, oacc[ni][3] * il1);
        *(__half2*)(aout + r0g + col) = p0;
        *(__half2*)(aout + r1g + col) = p1;
    }
}

// ---------------- SiLU(gate)*up (fp32 in, half out) ----------------
__global__ void __launch_bounds__(256) silu_kernel(const float* __restrict__ gu,
                                                   __half* __restrict__ act) {
    size_t idx = (size_t)blockIdx.x * 256 + threadIdx.x;
    int row = (int)(idx / (FFI / 4));
    int c   = (int)(idx % (FFI / 4));
    const float4 g = *(const float4*)(gu + (size_t)row * 2 * FFI + c * 4);
    const float4 u = *(const float4*)(gu + (size_t)row * 2 * FFI + FFI + c * 4);
    float rx = g.x / (1.0f + expf(-g.x)) * u.x;
    float ry = g.y / (1.0f + expf(-g.y)) * u.y;
    float rz = g.z / (1.0f + expf(-g.z)) * u.z;
    float rw = g.w / (1.0f + expf(-g.w)) * u.w;
    __half2 p0 = __floats2half2_rn(rx, ry);
    __half2 p1 = __floats2half2_rn(rz, rw);
    uint2 pk = make_uint2(*(uint32_t*)&p0, *(uint32_t*)&p1);
    *(uint2*)(act + (size_t)row * FFI + c * 4) = pk;
}

// ---------------- launch ----------------
extern "C" void kernel_launch(void* const* d_in, const int* in_sizes, int n_in,
                              void* d_out, int out_size) {
    const float* x    = (const float*)d_in[0];
    const float* ln1w = (const float*)d_in[1];
    const float* wqkv = (const float*)d_in[2];
    const float* wo   = (const float*)d_in[3];
    const float* ln2w = (const float*)d_in[4];
    const float* wgu  = (const float*)d_in[5];
    const float* wdn  = (const float*)d_in[6];
    const int*   pos  = (const int*)d_in[7];
    float* out = (float*)d_out;

    void *phH, *pqkv, *paoH, *ph1, *ph2H, *pgu, *pactH, *pwq, *pwo, *pwg, *pwd;
    cudaGetSymbolAddress(&phH,   g_hH);
    cudaGetSymbolAddress(&pqkv,  g_qkv);
    cudaGetSymbolAddress(&paoH,  g_aoutH);
    cudaGetSymbolAddress(&ph1,   g_h1);
    cudaGetSymbolAddress(&ph2H,  g_h2H);
    cudaGetSymbolAddress(&pgu,   g_gu);
    cudaGetSymbolAddress(&pactH, g_actH);
    cudaGetSymbolAddress(&pwq,   g_wqkvH);
    cudaGetSymbolAddress(&pwo,   g_woH);
    cudaGetSymbolAddress(&pwg,   g_wguH);
    cudaGetSymbolAddress(&pwd,   g_wdnH);
    __half* hH    = (__half*)phH;
    float*  qkv   = (float*)pqkv;
    __half* aoutH = (__half*)paoH;
    float*  h1    = (float*)ph1;
    __half* h2H   = (__half*)ph2H;
    float*  gu    = (float*)pgu;
    __half* actH  = (__half*)pactH;
    __half* wqkvH = (__half*)pwq;
    __half* woH   = (__half*)pwo;
    __half* wguH  = (__half*)pwg;
    __half* wdnH  = (__half*)pwd;

    cudaFuncSetAttribute(attn_kernel, cudaFuncAttributeMaxDynamicSharedMemorySize, ATT_SMEM);

    // 0. convert weights to fp16 once
    h2fcopy_kernel<<<(HID * QKV_N / 4) / 256, 256>>>(wqkv, wqkvH);
    h2fcopy_kernel<<<(HID * HID / 4) / 256, 256>>>(wo, woH);
    h2fcopy_kernel<<<(HID * 2 * FFI / 4) / 256, 256>>>(wgu, wguH);
    h2fcopy_kernel<<<(FFI * HID / 4) / 256, 256>>>(wdn, wdnH);

    // 1. h = rmsnorm(x) -> half
    rmsnorm_kernel<<<NT, 256>>>(x, ln1w, hH);
    // 2. qkv = h @ wqkv  (fp16 mma, fp32 out)
    f16gemm_kernel<0><<<dim3(QKV_N / 128, NT / 128), 256>>>(hH, wqkvH, nullptr, qkv, NT, QKV_N, HID);
    // 3. rope
    rope_kernel<<<dim3(NT, NH + NKV), 64>>>(qkv, pos);
    // 4. attention (fp16 tensor cores) -> half aout
    attn_kernel<<<dim3(SEQ / 64, NH, NB), 256, ATT_SMEM>>>(qkv, aoutH);
    // 5. h1 = x + aout @ wo
    f16gemm_kernel<1><<<dim3(HID / 128, NT / 128), 256>>>(aoutH, woH, x, h1, NT, HID, HID);
    // 6. h2 = rmsnorm(h1) -> half
    rmsnorm_kernel<<<NT, 256>>>(h1, ln2w, h2H);
    // 7. gu = h2 @ w_gate_up
    f16gemm_kernel<0><<<dim3(2 * FFI / 128, NT / 128), 256>>>(h2H, wguH, nullptr, gu, NT, 2 * FFI, HID);
    // 8. act = silu(gate)*up -> half
    silu_kernel<<<(NT * FFI / 4) / 256, 256>>>(gu, actH);
    // 9. out = h1 + act @ w_down
    f16gemm_kernel<1><<<dim3(HID / 128, NT / 128), 256>>>(actH, wdnH, h1, out, NT, HID, FFI);
}